// round 16
// baseline (speedup 1.0000x reference)
#include <cuda_runtime.h>
#include <cstdint>

#define BB 16
#define HH 512
#define WW 512
#define HW (HH*WW)
#define SEGY 8             // output rows per block
#define TR (SEGY + 30)     // 38 tile rows (15 halo each side)
#define NBANDS 64          // HH / SEGY
#define NBLK (BB*NBANDS)   // 1024 blocks

// Scratch (no allocations allowed -> __device__ globals)
__device__ float        g_part[NBLK*4];    // per-(b,band) partial sums
__device__ unsigned int g_count;           // completion counter (zero-init, self-reset)

// ---------------------------------------------------------------------------
// Fused kernel, 256 threads (8 warps), 8-row bands -> 1024 blocks so the
// grid can fill ~5 blocks/SM (occupancy was grid-limited at 512 blocks):
// mask tile -> packed-SIMD vertical 31-sum (u8 csum) -> single-pass per-row
// horizontal window via register/shuffle prefix -> fused log-softmax CE +
// wIoU -> band partials -> last-block-done final reduction (deterministic).
// Grid: (B, 64 y-bands of 8 rows); warp w = row y0+w.
__global__ __launch_bounds__(256, 5)
void fused_kernel(const float* __restrict__ pred, const int* __restrict__ mask32,
                  float* __restrict__ out) {
    const int tid = threadIdx.x;
    const int b   = blockIdx.x;
    const int y0  = blockIdx.y * SEGY;

    __shared__ unsigned char tile[TR][WW];      // mask halo tile (u8)
    __shared__ unsigned char csum[SEGY][WW];    // vertical 31-sums (u8, max 31)
    __shared__ int sflag;
    __shared__ float red[8][4];
    __shared__ float lossb[BB];
    __shared__ int slast;

    // --- dtype detection: int64 non-negative => all odd 32-bit words are 0 ---
    if (tid == 0) sflag = 0;
    __syncthreads();
    if (tid < 64) {
        int v = mask32[2 * tid + 1];
        if (v != 0) atomicOr(&sflag, 1);
    }
    __syncthreads();
    const bool is64 = (sflag == 0);

    // --- L2 prefetch of this block's pred rows (overlaps mask phases) ---
    {
        const float* pf0 = pred + ((size_t)(2 * b)    ) * HW + (size_t)y0 * WW + tid * 16;
        const float* pf1 = pred + ((size_t)(2 * b) + 1) * HW + (size_t)y0 * WW + tid * 16;
        asm volatile("prefetch.global.L2 [%0];" :: "l"(pf0));
        asm volatile("prefetch.global.L2 [%0];" :: "l"(pf1));
    }

    // --- cooperative tile load: row r = global row y0-15+r (zeros outside) ---
    if (!is64) {
        // int32: int4 = 4 columns; 128 int4 per row; 256 threads = 2 rows/iter
        const int* mb = mask32 + (size_t)b * HW;
        const int rr = tid >> 7;           // 0/1
        const int c4 = tid & 127;          // int4 index in row
        #pragma unroll
        for (int r0 = 0; r0 < TR; r0 += 2) {
            const int r = r0 + rr;
            const int y = y0 - 15 + r;
            unsigned u = 0;
            if ((unsigned)y < (unsigned)HH) {
                int4 v = ((const int4*)(mb + (size_t)y * WW))[c4];
                u = (unsigned)(v.x == 1) | ((unsigned)(v.y == 1) << 8)
                  | ((unsigned)(v.z == 1) << 16) | ((unsigned)(v.w == 1) << 24);
            }
            *(unsigned*)&tile[r][c4 * 4] = u;
        }
    } else {
        // int64: int4 = 2 columns; 256 int4 per row; 256 threads = 1 row/iter
        const int* mb = mask32 + ((size_t)b * HW) * 2;
        #pragma unroll 4
        for (int r = 0; r < TR; ++r) {
            const int y = y0 - 15 + r;
            unsigned short u = 0;
            if ((unsigned)y < (unsigned)HH) {
                int4 v = ((const int4*)(mb + (((size_t)y * WW) << 1)))[tid];
                u = (unsigned short)((unsigned)(v.x == 1) | ((unsigned)(v.z == 1) << 8));
            }
            *(unsigned short*)&tile[r][tid * 2] = u;
        }
    }
    __syncthreads();

    // --- phase 1: packed vertical sliding 31-sum, 4 columns/thread as u32 ---
    // Bytes are 0/1; packed byte sums <= 31 -> no carries, exact.
    // Thread t: u32-word t&127; half t>>7 -> output rows 0-3 / 4-7.
    {
        const int wcol = tid & 127;
        const int h4   = (tid >> 7) * 4;   // 0 or 4
        unsigned sum = 0;
        #pragma unroll
        for (int r = 0; r < 31; ++r)
            sum += *(const unsigned*)&tile[h4 + r][wcol * 4];
        #pragma unroll
        for (int i = 0; i < 4; ++i) {
            *(unsigned*)&csum[h4 + i][wcol * 4] = sum;
            if (i < 3)
                sum += *(const unsigned*)&tile[h4 + 31 + i][wcol * 4]
                     - *(const unsigned*)&tile[h4 + i][wcol * 4];
        }
    }
    __syncthreads();

    // --- phase 2: warp w handles row y0 + w (single pass) ---
    const int lane = tid & 31;
    const int w    = tid >> 5;
    const int y    = y0 + w;

    float a0 = 0.f, a1 = 0.f, a2 = 0.f, a3 = 0.f;
    {
        // colsum row: 16 u8 per thread (one uint4)
        uint4 csw = ((const uint4*)&csum[w][0])[lane];
        // mask row bytes: 16 u8 per thread
        uint4 mword = ((const uint4*)&tile[15 + w][0])[lane];
        const unsigned char* mbytes = (const unsigned char*)&mword;
        const unsigned char* cbytes = (const unsigned char*)&csw;

        // thread-local inclusive prefix of the 16 colsums
        int inc[16];
        {
            int run = 0;
            #pragma unroll
            for (int j = 0; j < 16; ++j) {
                run += (int)cbytes[j];
                inc[j] = run;
            }
        }
        // warp scan of thread totals
        int tot = inc[15], v = tot;
        #pragma unroll
        for (int o = 1; o < 32; o <<= 1) {
            int n = __shfl_up_sync(0xffffffffu, v, o);
            if (lane >= o) v += n;
        }
        const int base = v - tot;
        #pragma unroll
        for (int j = 0; j < 16; ++j) inc[j] += base;

        const float* p0base = pred + ((size_t)(2 * b)    ) * HW + (size_t)y * WW;
        const float* p1base = pred + ((size_t)(2 * b) + 1) * HW + (size_t)y * WW;

        #pragma unroll
        for (int c = 0; c < 2; ++c) {
            float4 q0[2], q1[2];
            q0[0] = ((const float4*)p0base)[lane * 4 + c * 2];
            q0[1] = ((const float4*)p0base)[lane * 4 + c * 2 + 1];
            q1[0] = ((const float4*)p1base)[lane * 4 + c * 2];
            q1[1] = ((const float4*)p1base)[lane * 4 + c * 2 + 1];
            const float* f0 = (const float*)q0;
            const float* f1 = (const float*)q1;

            #pragma unroll
            for (int jj = 0; jj < 8; ++jj) {
                const int j = c * 8 + jj;
                // P[x+15]: own inc[15] at j==0; else lane+1's inc[j-1] (lane31 -> own inc[15])
                int Ph;
                if (j == 0) {
                    Ph = inc[15];
                } else {
                    int s = __shfl_down_sync(0xffffffffu, inc[j - 1], 1);
                    Ph = (lane == 31) ? inc[15] : s;
                }
                // P[x-16]: lane-1's inc[j] (lane0 -> 0)
                int t = __shfl_up_sync(0xffffffffu, inc[j], 1);
                int Pl = (lane == 0) ? 0 : t;

                float pooled = (float)(Ph - Pl) * (1.0f / 961.0f);

                unsigned m = mbytes[j];
                float mf = (float)m;

                float d = f1[jj] - f0[jj];
                float a = fabsf(d);
                float e = __expf(-a);
                float l = __logf(1.0f + e);
                bool dpos = (d >= 0.f);

                float wbce   = l + ((dpos == (m != 0u)) ? 0.f : a);
                float p1prob = __fdividef(dpos ? 1.0f : e, 1.0f + e);
                float weit   = 1.0f + 5.0f * fabsf(pooled - mf);

                a0 += weit;
                a1 += weit * wbce;
                a2 += p1prob * mf * weit;
                a3 += (p1prob + mf) * weit;
            }
        }
    }

    // --- warp reduce, then cross-warp reduce to one band partial ---
    #pragma unroll
    for (int o = 16; o > 0; o >>= 1) {
        a0 += __shfl_down_sync(0xffffffffu, a0, o);
        a1 += __shfl_down_sync(0xffffffffu, a1, o);
        a2 += __shfl_down_sync(0xffffffffu, a2, o);
        a3 += __shfl_down_sync(0xffffffffu, a3, o);
    }
    if (lane == 0) { red[w][0] = a0; red[w][1] = a1; red[w][2] = a2; red[w][3] = a3; }
    __syncthreads();

    if (tid == 0) slast = 0;

    if (w == 0) {
        float r0 = (lane < 8) ? red[lane][0] : 0.f;
        float r1 = (lane < 8) ? red[lane][1] : 0.f;
        float r2 = (lane < 8) ? red[lane][2] : 0.f;
        float r3 = (lane < 8) ? red[lane][3] : 0.f;
        #pragma unroll
        for (int o = 4; o > 0; o >>= 1) {
            r0 += __shfl_down_sync(0xffffffffu, r0, o);
            r1 += __shfl_down_sync(0xffffffffu, r1, o);
            r2 += __shfl_down_sync(0xffffffffu, r2, o);
            r3 += __shfl_down_sync(0xffffffffu, r3, o);
        }
        if (lane == 0) {
            float* p = g_part + ((size_t)(b * NBANDS) + blockIdx.y) * 4;
            p[0] = r0; p[1] = r1; p[2] = r2; p[3] = r3;
            __threadfence();
            unsigned int old = atomicAdd(&g_count, 1u);
            if (old == NBLK - 1) {
                __threadfence();
                slast = 1;
            }
        }
    }
    __syncthreads();

    // --- last block: final reduction (deterministic), write out, reset ---
    if (slast) {
        #pragma unroll
        for (int pass = 0; pass < 2; ++pass) {
            const int bb = w * 2 + pass;      // warp w -> batches 2w, 2w+1
            const float4 va = ((const float4*)g_part)[bb * NBANDS + lane];
            const float4 vb = ((const float4*)g_part)[bb * NBANDS + 32 + lane];
            float s0 = va.x + vb.x, s1 = va.y + vb.y;
            float s2 = va.z + vb.z, s3 = va.w + vb.w;
            #pragma unroll
            for (int o = 16; o > 0; o >>= 1) {
                s0 += __shfl_down_sync(0xffffffffu, s0, o);
                s1 += __shfl_down_sync(0xffffffffu, s1, o);
                s2 += __shfl_down_sync(0xffffffffu, s2, o);
                s3 += __shfl_down_sync(0xffffffffu, s3, o);
            }
            if (lane == 0) {
                float wbce  = s1 / s0;
                float inter = s2;
                float uni   = s3 - s2;             // cardinality - inter
                float wiou  = 1.f - (inter + 1.f) / (uni + 1.f);
                lossb[bb] = wbce + wiou;
            }
        }
        __syncthreads();
        if (tid == 0) {
            float t = 0.f;
            #pragma unroll
            for (int i = 0; i < BB; ++i) t += lossb[i];
            out[0] = t * (1.f / (float)BB);
            atomicExch(&g_count, 0u);              // reset for next graph replay
        }
    }
}

// ---------------------------------------------------------------------------
extern "C" void kernel_launch(void* const* d_in, const int* in_sizes, int n_in,
                              void* d_out, int out_size) {
    const float* pred   = (const float*)d_in[0];
    const int*   mask32 = (const int*)d_in[1];   // 32-bit view; dtype detected in-kernel
    float* out = (float*)d_out;

    // Max the smem carveout (idempotent; not an allocation; capture-legal).
    cudaFuncSetAttribute(fused_kernel,
                         cudaFuncAttributePreferredSharedMemoryCarveout, 100);

    fused_kernel<<<dim3(BB, NBANDS), 256>>>(pred, mask32, out);
}

// round 17
// speedup vs baseline: 1.2780x; 1.2780x over previous
#include <cuda_runtime.h>
#include <cstdint>

#define BB 16
#define HH 512
#define WW 512
#define HW (HH*WW)
#define SEGY 16            // output rows per block
#define TR (SEGY + 30)     // 46 tile rows (15 halo each side)
#define NBANDS 32          // HH / SEGY
#define NBLK (BB*NBANDS)   // 512 blocks

// Scratch (no allocations allowed -> __device__ globals)
__device__ float        g_part[NBLK*4];    // per-(b,band) partial sums
__device__ unsigned int g_count;           // completion counter (zero-init, self-reset)

// ---------------------------------------------------------------------------
// Fused kernel, 256 threads (8 warps), 4 blocks/SM:
// mask tile -> packed-SIMD vertical 31-sum (u8 csum) -> per-row horizontal
// window via SCAN-FREE sliding window (win(16L) = tot_L + tot_{L-1} -
// c[16(L-1)]; then win += c_hi - c_lo in registers) -> fused log-softmax CE
// + wIoU -> band partials -> last-block-done final reduction (deterministic).
// Grid: (B, 32 y-bands of 16 rows); warp w handles rows w and w+8.
__global__ __launch_bounds__(256, 4)
void fused_kernel(const float* __restrict__ pred, const int* __restrict__ mask32,
                  float* __restrict__ out) {
    const int tid = threadIdx.x;
    const int b   = blockIdx.x;
    const int y0  = blockIdx.y * SEGY;

    __shared__ unsigned char tile[TR][WW];      // mask halo tile (u8)
    __shared__ unsigned char csum[SEGY][WW];    // vertical 31-sums (u8, max 31)
    __shared__ int sflag;
    __shared__ float red[8][4];
    __shared__ float lossb[BB];
    __shared__ int slast;

    // --- dtype detection: int64 non-negative => all odd 32-bit words are 0 ---
    if (tid == 0) sflag = 0;
    __syncthreads();
    if (tid < 64) {
        int v = mask32[2 * tid + 1];
        if (v != 0) atomicOr(&sflag, 1);
    }
    __syncthreads();
    const bool is64 = (sflag == 0);

    // --- cooperative tile load: row r = global row y0-15+r (zeros outside) ---
    if (!is64) {
        // int32: int4 = 4 columns; 128 int4 per row; 256 threads = 2 rows/iter
        const int* mb = mask32 + (size_t)b * HW;
        const int rr = tid >> 7;           // 0/1
        const int c4 = tid & 127;          // int4 index in row
        #pragma unroll
        for (int r0 = 0; r0 < TR; r0 += 2) {
            const int r = r0 + rr;
            const int y = y0 - 15 + r;
            unsigned u = 0;
            if ((unsigned)y < (unsigned)HH) {
                int4 v = ((const int4*)(mb + (size_t)y * WW))[c4];
                u = (unsigned)(v.x == 1) | ((unsigned)(v.y == 1) << 8)
                  | ((unsigned)(v.z == 1) << 16) | ((unsigned)(v.w == 1) << 24);
            }
            *(unsigned*)&tile[r][c4 * 4] = u;
        }
    } else {
        // int64: int4 = 2 columns; 256 int4 per row; 256 threads = 1 row/iter
        const int* mb = mask32 + ((size_t)b * HW) * 2;
        #pragma unroll 4
        for (int r = 0; r < TR; ++r) {
            const int y = y0 - 15 + r;
            unsigned short u = 0;
            if ((unsigned)y < (unsigned)HH) {
                int4 v = ((const int4*)(mb + (((size_t)y * WW) << 1)))[tid];
                u = (unsigned short)((unsigned)(v.x == 1) | ((unsigned)(v.z == 1) << 8));
            }
            *(unsigned short*)&tile[r][tid * 2] = u;
        }
    }
    __syncthreads();

    // --- phase 1: packed vertical sliding 31-sum, 4 columns/thread as u32 ---
    // Bytes are 0/1; packed byte sums <= 31 -> no carries, exact.
    {
        const int wcol = tid & 127;
        const int h8   = (tid >> 7) * 8;   // 0 or 8
        unsigned sum = 0;
        #pragma unroll
        for (int r = 0; r < 31; ++r)
            sum += *(const unsigned*)&tile[h8 + r][wcol * 4];
        #pragma unroll
        for (int i = 0; i < 8; ++i) {
            *(unsigned*)&csum[h8 + i][wcol * 4] = sum;
            if (i < 7)
                sum += *(const unsigned*)&tile[h8 + 31 + i][wcol * 4]
                     - *(const unsigned*)&tile[h8 + i][wcol * 4];
        }
    }
    __syncthreads();

    // --- phase 2: warp w handles rows y0+w and y0+w+8 ---
    const int lane = tid & 31;
    const int w    = tid >> 5;

    float a0 = 0.f, a1 = 0.f, a2 = 0.f, a3 = 0.f;

    #pragma unroll
    for (int pass = 0; pass < 2; ++pass) {
        const int rw = w + pass * 8;
        const int y  = y0 + rw;

        // colsum row: 16 u8 per thread (one uint4)
        uint4 csw = ((const uint4*)&csum[rw][0])[lane];
        // mask row bytes: 16 u8 per thread
        uint4 mword = ((const uint4*)&tile[15 + rw][0])[lane];
        const unsigned char* mbytes = (const unsigned char*)&mword;

        // thread total of 16 colsum bytes (dp4a; exact, bytes <= 31)
        const int ones = 0x01010101;
        int tot = __dp4a((int)csw.x, ones, 0);
        tot = __dp4a((int)csw.y, ones, tot);
        tot = __dp4a((int)csw.z, ones, tot);
        tot = __dp4a((int)csw.w, ones, tot);

        // win at j=0 (x = 16*lane): P[x+15]-P[x-16] = tot + prev_tot - prev_c0
        int c0 = (int)(csw.x & 0xffu);
        int up = __shfl_up_sync(0xffffffffu, tot - c0, 1);
        int win = tot + ((lane == 0) ? 0 : up);

        // neighbor colsum byte-words for the sliding window
        unsigned hi[4], lo[4];
        hi[0] = __shfl_down_sync(0xffffffffu, csw.x, 1);
        hi[1] = __shfl_down_sync(0xffffffffu, csw.y, 1);
        hi[2] = __shfl_down_sync(0xffffffffu, csw.z, 1);
        hi[3] = __shfl_down_sync(0xffffffffu, csw.w, 1);
        if (lane == 31) { hi[0] = hi[1] = hi[2] = hi[3] = 0u; }  // clamp at x=511
        lo[0] = __shfl_up_sync(0xffffffffu, csw.x, 1);
        lo[1] = __shfl_up_sync(0xffffffffu, csw.y, 1);
        lo[2] = __shfl_up_sync(0xffffffffu, csw.z, 1);
        lo[3] = __shfl_up_sync(0xffffffffu, csw.w, 1);
        if (lane == 0) { lo[0] = lo[1] = lo[2] = lo[3] = 0u; }   // zeros below x=0

        const float* p0base = pred + ((size_t)(2 * b)    ) * HW + (size_t)y * WW;
        const float* p1base = pred + ((size_t)(2 * b) + 1) * HW + (size_t)y * WW;

        #pragma unroll
        for (int c = 0; c < 2; ++c) {
            float4 q0[2], q1[2];
            q0[0] = ((const float4*)p0base)[lane * 4 + c * 2];
            q0[1] = ((const float4*)p0base)[lane * 4 + c * 2 + 1];
            q1[0] = ((const float4*)p1base)[lane * 4 + c * 2];
            q1[1] = ((const float4*)p1base)[lane * 4 + c * 2 + 1];
            const float* f0 = (const float*)q0;
            const float* f1 = (const float*)q1;

            #pragma unroll
            for (int jj = 0; jj < 8; ++jj) {
                const int j = c * 8 + jj;
                if (j > 0) {
                    // win(x) - win(x-1) = c[x+15] - c[x-16]
                    int chi = (int)((hi[(j - 1) >> 2] >> (((j - 1) & 3) * 8)) & 0xffu);
                    int clo = (int)((lo[j >> 2]       >> ((j & 3) * 8))       & 0xffu);
                    win += chi - clo;
                }

                float pooled = (float)win * (1.0f / 961.0f);

                unsigned m = mbytes[j];
                float mf = (float)m;

                float d = f1[jj] - f0[jj];
                float a = fabsf(d);
                float e = __expf(-a);
                float l = __logf(1.0f + e);
                bool dpos = (d >= 0.f);

                float wbce   = l + ((dpos == (m != 0u)) ? 0.f : a);
                float p1prob = __fdividef(dpos ? 1.0f : e, 1.0f + e);
                float weit   = 1.0f + 5.0f * fabsf(pooled - mf);

                a0 += weit;
                a1 += weit * wbce;
                a2 += p1prob * mf * weit;
                a3 += (p1prob + mf) * weit;
            }
        }
    }

    // --- warp reduce, then cross-warp reduce to one band partial ---
    #pragma unroll
    for (int o = 16; o > 0; o >>= 1) {
        a0 += __shfl_down_sync(0xffffffffu, a0, o);
        a1 += __shfl_down_sync(0xffffffffu, a1, o);
        a2 += __shfl_down_sync(0xffffffffu, a2, o);
        a3 += __shfl_down_sync(0xffffffffu, a3, o);
    }
    if (lane == 0) { red[w][0] = a0; red[w][1] = a1; red[w][2] = a2; red[w][3] = a3; }
    __syncthreads();

    if (tid == 0) slast = 0;

    if (w == 0) {
        float r0 = (lane < 8) ? red[lane][0] : 0.f;
        float r1 = (lane < 8) ? red[lane][1] : 0.f;
        float r2 = (lane < 8) ? red[lane][2] : 0.f;
        float r3 = (lane < 8) ? red[lane][3] : 0.f;
        #pragma unroll
        for (int o = 4; o > 0; o >>= 1) {
            r0 += __shfl_down_sync(0xffffffffu, r0, o);
            r1 += __shfl_down_sync(0xffffffffu, r1, o);
            r2 += __shfl_down_sync(0xffffffffu, r2, o);
            r3 += __shfl_down_sync(0xffffffffu, r3, o);
        }
        if (lane == 0) {
            float* p = g_part + ((size_t)(b * NBANDS) + blockIdx.y) * 4;
            p[0] = r0; p[1] = r1; p[2] = r2; p[3] = r3;
            __threadfence();
            unsigned int old = atomicAdd(&g_count, 1u);
            if (old == NBLK - 1) {
                __threadfence();
                slast = 1;
            }
        }
    }
    __syncthreads();

    // --- last block: final reduction (deterministic), write out, reset ---
    if (slast) {
        #pragma unroll
        for (int pass = 0; pass < 2; ++pass) {
            const int bb = w + pass * 8;      // warp w -> batches w, w+8
            const float4 vv = ((const float4*)g_part)[bb * NBANDS + lane];
            float s0 = vv.x, s1 = vv.y, s2 = vv.z, s3 = vv.w;
            #pragma unroll
            for (int o = 16; o > 0; o >>= 1) {
                s0 += __shfl_down_sync(0xffffffffu, s0, o);
                s1 += __shfl_down_sync(0xffffffffu, s1, o);
                s2 += __shfl_down_sync(0xffffffffu, s2, o);
                s3 += __shfl_down_sync(0xffffffffu, s3, o);
            }
            if (lane == 0) {
                float wbce  = s1 / s0;
                float inter = s2;
                float uni   = s3 - s2;             // cardinality - inter
                float wiou  = 1.f - (inter + 1.f) / (uni + 1.f);
                lossb[bb] = wbce + wiou;
            }
        }
        __syncthreads();
        if (tid == 0) {
            float t = 0.f;
            #pragma unroll
            for (int i = 0; i < BB; ++i) t += lossb[i];
            out[0] = t * (1.f / (float)BB);
            atomicExch(&g_count, 0u);              // reset for next graph replay
        }
    }
}

// ---------------------------------------------------------------------------
extern "C" void kernel_launch(void* const* d_in, const int* in_sizes, int n_in,
                              void* d_out, int out_size) {
    const float* pred   = (const float*)d_in[0];
    const int*   mask32 = (const int*)d_in[1];   // 32-bit view; dtype detected in-kernel
    float* out = (float*)d_out;

    fused_kernel<<<dim3(BB, NBANDS), 256>>>(pred, mask32, out);
}